// round 9
// baseline (speedup 1.0000x reference)
#include <cuda_runtime.h>
#include <cstdint>
#include <math.h>

#define NLEV 24
#define CAPACITY (1u << 18)
#define MAXN 262144

// 48 feature rows, transposed layout [2*NLEV][MAXN] for coalesced access.
__device__ float g_enc[2 * NLEV * MAXN];

union F2U { float2 f; unsigned long long u; };

// Packed dual-lane FMA / MUL (Blackwell f32x2 pipes).
__device__ __forceinline__ float2 ffma2(float2 a, float2 b, float2 c) {
    F2U A, B, C, D;
    A.f = a; B.f = b; C.f = c;
    asm("fma.rn.f32x2 %0, %1, %2, %3;" : "=l"(D.u) : "l"(A.u), "l"(B.u), "l"(C.u));
    return D.f;
}
__device__ __forceinline__ float2 mul2(float2 a, float2 b) {
    F2U A, B, D;
    A.f = a; B.f = b;
    asm("mul.rn.f32x2 %0, %1, %2;" : "=l"(D.u) : "l"(A.u), "l"(B.u));
    return D.f;
}
__device__ __forceinline__ float2 f2(float a, float b) { return make_float2(a, b); }

__device__ __forceinline__ float frcp(float x) {
    float r; asm("rcp.approx.f32 %0, %1;" : "=f"(r) : "f"(x)); return r;
}

// Packed-pair GELU, erf via A&S 7.1.25 (3-term, |err| <= 2.5e-5 abs).
// Validated in R7: end-to-end rel_err 1.55e-7 (threshold 1e-3).
__device__ __forceinline__ float2 gelu2(float2 v) {
    const float2 zc = f2(0.70710678118654752f, 0.70710678118654752f);
    float2 z  = mul2(v, zc);
    float2 az = f2(fabsf(z.x), fabsf(z.y));
    float2 den = ffma2(f2(0.47047f, 0.47047f), az, f2(1.0f, 1.0f));
    float2 t = f2(frcp(den.x), frcp(den.y));
    float2 p = ffma2(f2(0.7478556f, 0.7478556f), t, f2(-0.0958798f, -0.0958798f));
    p = ffma2(p, t, f2(0.3480242f, 0.3480242f));
    p = mul2(p, t);
    float2 zz = mul2(az, az);
    float2 e = f2(__expf(-zz.x), __expf(-zz.y));
    float2 pe = mul2(p, e);
    float2 er = f2(copysignf(1.0f - pe.x, z.x), copysignf(1.0f - pe.y, z.y));
    float2 hv = mul2(v, f2(0.5f, 0.5f));
    return ffma2(hv, er, hv);
}

// ======================= K1: permutohedral encoding =======================

__global__ __launch_bounds__(256, 4)
void enc_kernel(const float* __restrict__ points,
                const int*   __restrict__ iter_nr,
                const float* __restrict__ tables,
                const float* __restrict__ shifts,
                int N)
{
    __shared__ float s_shift[NLEV * 3];
    __shared__ float s_invsc[NLEV];
    __shared__ float s_win[NLEV];
    __shared__ int   s_nlev;

    const int tid = threadIdx.x;
    if (tid < NLEV * 3) s_shift[tid] = shifts[tid];
    if (tid < NLEV) {
        // SCALES = geomspace(1, 1e-4, 24) = 10^(i * (-4/23)) in float64 -> f32
        double step = -4.0 / 23.0;
        float sc = (float)pow(10.0, step * (double)tid);
        s_invsc[tid] = 1.0f / sc;
        float t = fminf(fmaxf((float)iter_nr[0] / 10000.0f, 0.0f), 1.0f);
        float alpha = (0.3f + 0.7f * t) * (float)NLEV;
        float x = fminf(fmaxf(alpha - (float)tid, 0.0f), 1.0f);
        s_win[tid] = 0.5f * (1.0f - cosf(3.14159265358979323846f * x));
        if (tid == 0) {
            int na = (int)ceilf(alpha);
            if (na > NLEV) na = NLEV;
            if (na < 0) na = 0;
            s_nlev = na;
        }
    }
    __syncthreads();

    const int n = blockIdx.x * 256 + tid;
    if (n >= N) return;
    const int nlev = s_nlev;

    const float p0 = __ldg(points + n * 3 + 0);
    const float p1 = __ldg(points + n * 3 + 1);
    const float p2 = __ldg(points + n * 3 + 2);
    const float2* tab2 = (const float2*)tables;

    const float SF0 = 2.30940107675850341796875f;  // 4*sqrt(2/3)/sqrt(1*2)
    const float SF1 = 1.33333333333333333f;
    const float SF2 = 0.94280904158206336f;
    const float RM  = 12582912.0f;                 // 1.5 * 2^23
    const int   RI  = 0x4B400000;                  // bit pattern of RM

    #pragma unroll 1
    for (int lev = 0; lev < nlev; ++lev) {
        const float inv = s_invsc[lev];
        const float cf0 = fmaf(p0, inv, s_shift[lev * 3 + 0]) * SF0;
        const float cf1 = fmaf(p1, inv, s_shift[lev * 3 + 1]) * SF1;
        const float cf2 = fmaf(p2, inv, s_shift[lev * 3 + 2]) * SF2;

        const float S2 = cf2;
        const float S1 = cf2 + cf1;
        const float S0 = S1 + cf0;

        float e[4];
        e[0] = S0;
        e[1] = S1 - cf0;
        e[2] = S2 - 2.0f * cf1;
        e[3] = -3.0f * cf2;

        float u[4];
        int   m[4];
        #pragma unroll
        for (int i = 0; i < 4; i++) {
            const float q = fmaf(e[i], 0.25f, RM);     // round-half-even
            m[i] = __float_as_int(q) - RI;             // rint(e/4) as int
            const float t = q - RM;                    // rint(e/4) float (exact)
            u[i] = fmaf(e[i], 0.25f, -t);              // delta (exact)
        }

        const int sumv = m[0] + m[1] + m[2] + m[3];

        // rank via 6 antisymmetric compares (stable argsort(argsort(-u)))
        const int t01 = (u[1] > u[0]);
        const int t02 = (u[2] > u[0]);
        const int t03 = (u[3] > u[0]);
        const int t12 = (u[2] > u[1]);
        const int t13 = (u[3] > u[1]);
        const int t23 = (u[3] > u[2]);

        int rk[4];
        rk[0] = sumv +     t01 + t02 + t03;
        rk[1] = sumv + 1 - t01 + t12 + t13;
        rk[2] = sumv + 2 - t02 - t12 + t23;
        rk[3] = sumv + 3 - t03 - t13 - t23;

        #pragma unroll
        for (int i = 0; i < 4; i++) {
            if (rk[i] < 0)      { rk[i] += 4; m[i] += 1; u[i] -= 1.0f; }
            else if (rk[i] > 3) { rk[i] -= 4; m[i] -= 1; u[i] += 1.0f; }
        }

        // barycentric weights
        float bq0 = 0.f, bq1 = 0.f, bq2 = 0.f, bq3 = 0.f, bq4 = 0.f;
        #pragma unroll
        for (int i = 0; i < 4; i++) {
            const int id = 3 - rk[i];
            const float dv = u[i];
            if (id == 0)      { bq0 += dv; bq1 -= dv; }
            else if (id == 1) { bq1 += dv; bq2 -= dv; }
            else if (id == 2) { bq2 += dv; bq3 -= dv; }
            else              { bq3 += dv; bq4 -= dv; }
        }
        const float wl = s_win[lev];
        float w0 = (bq0 + 1.0f + bq4) * wl;
        float w1 = bq1 * wl;
        float w2 = bq2 * wl;
        float w3 = bq3 * wl;

        // vertex keys: key_i(k) = 4*m_i + ((k + rk_i) & 3) - rk_i
        const int b0 = 4 * m[0] - rk[0];
        const int b1 = 4 * m[1] - rk[1];
        const int b2 = 4 * m[2] - rk[2];
        const float2* tab = tab2 + (size_t)lev * CAPACITY;

        uint32_t idx[4];
        #pragma unroll
        for (int k = 0; k < 4; k++) {
            const uint32_t k0 = (uint32_t)(b0 + ((k + rk[0]) & 3));
            const uint32_t k1 = (uint32_t)(b1 + ((k + rk[1]) & 3));
            const uint32_t k2 = (uint32_t)(b2 + ((k + rk[2]) & 3));
            const uint32_t h = k0 ^ (k1 * 2654435761u) ^ (k2 * 805459861u);
            idx[k] = h & (CAPACITY - 1u);
        }
        const float2 g0 = __ldg(tab + idx[0]);
        const float2 g1 = __ldg(tab + idx[1]);
        const float2 g2 = __ldg(tab + idx[2]);
        const float2 g3 = __ldg(tab + idx[3]);

        float f0 = g0.x * w0, fy = g0.y * w0;
        f0 = fmaf(g1.x, w1, f0); fy = fmaf(g1.y, w1, fy);
        f0 = fmaf(g2.x, w2, f0); fy = fmaf(g2.y, w2, fy);
        f0 = fmaf(g3.x, w3, f0); fy = fmaf(g3.y, w3, fy);

        // transposed, coalesced stores
        g_enc[(size_t)(2 * lev) * MAXN + n]     = f0;
        g_enc[(size_t)(2 * lev + 1) * MAXN + n] = fy;
    }
}

// ================== K2: the MLP (2 points per thread) ==================

#define MBLK 128

__global__ __launch_bounds__(MBLK, 3)
void mlp_kernel(const float* __restrict__ points,
                const int*   __restrict__ iter_nr,
                const float* __restrict__ w1, const float* __restrict__ b1,
                const float* __restrict__ w2, const float* __restrict__ b2,
                const float* __restrict__ w3, const float* __restrict__ b3,
                const float* __restrict__ w4, const float* __restrict__ b4,
                float* __restrict__ out, int N)
{
    __shared__ float4 s_w1[51 * 8];
    __shared__ float4 s_w2[32 * 8];
    __shared__ float4 s_w3[32 * 8];
    __shared__ float4 s_w4g[32 * 8];    // geom cols 1..32
    __shared__ float  s_w4s[32];        // sdf column 0
    __shared__ float2 s_b1[16];
    __shared__ float2 s_b2[16];
    __shared__ float2 s_b3[16];
    __shared__ float  s_b4[33];
    __shared__ int    s_nlev;

    const int tid = threadIdx.x;

    {
        const float4* g1 = (const float4*)w1;
        const float4* g2 = (const float4*)w2;
        const float4* g3 = (const float4*)w3;
        for (int i = tid; i < 51 * 8; i += MBLK) s_w1[i] = g1[i];
        for (int i = tid; i < 32 * 8; i += MBLK) s_w2[i] = g2[i];
        for (int i = tid; i < 32 * 8; i += MBLK) s_w3[i] = g3[i];
    }
    {
        float* w4g = (float*)s_w4g;
        for (int i = tid; i < 32 * 33; i += MBLK) {
            int r = i / 33, c = i - r * 33;
            float v = w4[i];
            if (c == 0) s_w4s[r] = v; else w4g[r * 32 + (c - 1)] = v;
        }
    }
    if (tid < 16) {
        s_b1[tid] = ((const float2*)b1)[tid];
        s_b2[tid] = ((const float2*)b2)[tid];
        s_b3[tid] = ((const float2*)b3)[tid];
    }
    if (tid < 33) s_b4[tid] = b4[tid];
    if (tid == 0) {
        float t = fminf(fmaxf((float)iter_nr[0] / 10000.0f, 0.0f), 1.0f);
        float alpha = (0.3f + 0.7f * t) * (float)NLEV;
        int na = (int)ceilf(alpha);
        if (na > NLEV) na = NLEV;
        if (na < 0) na = 0;
        s_nlev = na;
    }
    __syncthreads();

    const int base = blockIdx.x * (MBLK * 2);
    const int n0 = base + tid;
    const int n1 = base + MBLK + tid;
    const bool a0 = (n0 < N);
    const bool a1 = (n1 < N);
    const int m0 = a0 ? n0 : (N - 1);
    const int m1 = a1 ? n1 : (N - 1);
    const int nlev = s_nlev;

    const float pA0 = __ldg(points + m0 * 3 + 0);
    const float pA1 = __ldg(points + m0 * 3 + 1);
    const float pA2 = __ldg(points + m0 * 3 + 2);
    const float pB0 = __ldg(points + m1 * 3 + 0);
    const float pB1 = __ldg(points + m1 * 3 + 1);
    const float pB2 = __ldg(points + m1 * 3 + 2);

    // ---- layer-1 accumulators, seeded with bias + point*0.001 rows (48..50)
    float2 h1a[16], h1b[16];
    {
        const float2 xaA = f2(pA0 * 0.001f, pA0 * 0.001f);
        const float2 xbA = f2(pA1 * 0.001f, pA1 * 0.001f);
        const float2 xcA = f2(pA2 * 0.001f, pA2 * 0.001f);
        const float2 xaB = f2(pB0 * 0.001f, pB0 * 0.001f);
        const float2 xbB = f2(pB1 * 0.001f, pB1 * 0.001f);
        const float2 xcB = f2(pB2 * 0.001f, pB2 * 0.001f);
        const float4* wa = s_w1 + 48 * 8;
        const float4* wb = s_w1 + 49 * 8;
        const float4* wc = s_w1 + 50 * 8;
        #pragma unroll
        for (int q = 0; q < 8; q++) {
            float4 A = wa[q], B = wb[q], C = wc[q];
            float2 A0 = f2(A.x, A.y), A1 = f2(A.z, A.w);
            float2 B0 = f2(B.x, B.y), B1 = f2(B.z, B.w);
            float2 C0 = f2(C.x, C.y), C1 = f2(C.z, C.w);
            float2 v;
            v = ffma2(xaA, A0, s_b1[2*q]);   v = ffma2(xbA, B0, v); h1a[2*q]   = ffma2(xcA, C0, v);
            v = ffma2(xaA, A1, s_b1[2*q+1]); v = ffma2(xbA, B1, v); h1a[2*q+1] = ffma2(xcA, C1, v);
            v = ffma2(xaB, A0, s_b1[2*q]);   v = ffma2(xbB, B0, v); h1b[2*q]   = ffma2(xcB, C0, v);
            v = ffma2(xaB, A1, s_b1[2*q+1]); v = ffma2(xbB, B1, v); h1b[2*q+1] = ffma2(xcB, C1, v);
        }
    }

    // ---- fold encoded features (L2-hot coalesced reads; LDS shared by 2 pts)
    #pragma unroll 1
    for (int lev = 0; lev < nlev; ++lev) {
        const float* encx = g_enc + (size_t)(2 * lev) * MAXN;
        const float* ency = encx + MAXN;
        const float fxA = encx[m0], fyA = ency[m0];
        const float fxB = encx[m1], fyB = ency[m1];
        const float2 f0A = f2(fxA, fxA), f1A = f2(fyA, fyA);
        const float2 f0B = f2(fxB, fxB), f1B = f2(fyB, fyB);
        const float4* ra = s_w1 + (2 * lev) * 8;
        #pragma unroll
        for (int q = 0; q < 8; q++) {
            float4 A = ra[q];       // row 2*lev
            float4 B = ra[q + 8];   // row 2*lev+1
            float2 A0 = f2(A.x, A.y), A1 = f2(A.z, A.w);
            float2 B0 = f2(B.x, B.y), B1 = f2(B.z, B.w);
            h1a[2*q]   = ffma2(f1A, B0, ffma2(f0A, A0, h1a[2*q]));
            h1a[2*q+1] = ffma2(f1A, B1, ffma2(f0A, A1, h1a[2*q+1]));
            h1b[2*q]   = ffma2(f1B, B0, ffma2(f0B, A0, h1b[2*q]));
            h1b[2*q+1] = ffma2(f1B, B1, ffma2(f0B, A1, h1b[2*q+1]));
        }
    }

    // ---- layers 2..4 ----
    #pragma unroll
    for (int q = 0; q < 16; q++) { h1a[q] = gelu2(h1a[q]); h1b[q] = gelu2(h1b[q]); }

    float2 h2a[16], h2b[16];
    #pragma unroll
    for (int q = 0; q < 16; q++) { h2a[q] = s_b2[q]; h2b[q] = s_b2[q]; }
    #pragma unroll
    for (int i = 0; i < 16; i++) {
        const float2 xaA = f2(h1a[i].x, h1a[i].x), xbA = f2(h1a[i].y, h1a[i].y);
        const float2 xaB = f2(h1b[i].x, h1b[i].x), xbB = f2(h1b[i].y, h1b[i].y);
        const float4* wr0 = s_w2 + (2 * i) * 8;
        const float4* wr1 = wr0 + 8;
        #pragma unroll
        for (int q = 0; q < 8; q++) {
            float4 A = wr0[q], B = wr1[q];
            float2 A0 = f2(A.x, A.y), A1 = f2(A.z, A.w);
            float2 B0 = f2(B.x, B.y), B1 = f2(B.z, B.w);
            h2a[2*q]   = ffma2(xbA, B0, ffma2(xaA, A0, h2a[2*q]));
            h2a[2*q+1] = ffma2(xbA, B1, ffma2(xaA, A1, h2a[2*q+1]));
            h2b[2*q]   = ffma2(xbB, B0, ffma2(xaB, A0, h2b[2*q]));
            h2b[2*q+1] = ffma2(xbB, B1, ffma2(xaB, A1, h2b[2*q+1]));
        }
    }
    #pragma unroll
    for (int q = 0; q < 16; q++) { h2a[q] = gelu2(h2a[q]); h2b[q] = gelu2(h2b[q]); }

    #pragma unroll
    for (int q = 0; q < 16; q++) { h1a[q] = s_b3[q]; h1b[q] = s_b3[q]; }
    #pragma unroll
    for (int i = 0; i < 16; i++) {
        const float2 xaA = f2(h2a[i].x, h2a[i].x), xbA = f2(h2a[i].y, h2a[i].y);
        const float2 xaB = f2(h2b[i].x, h2b[i].x), xbB = f2(h2b[i].y, h2b[i].y);
        const float4* wr0 = s_w3 + (2 * i) * 8;
        const float4* wr1 = wr0 + 8;
        #pragma unroll
        for (int q = 0; q < 8; q++) {
            float4 A = wr0[q], B = wr1[q];
            float2 A0 = f2(A.x, A.y), A1 = f2(A.z, A.w);
            float2 B0 = f2(B.x, B.y), B1 = f2(B.z, B.w);
            h1a[2*q]   = ffma2(xbA, B0, ffma2(xaA, A0, h1a[2*q]));
            h1a[2*q+1] = ffma2(xbA, B1, ffma2(xaA, A1, h1a[2*q+1]));
            h1b[2*q]   = ffma2(xbB, B0, ffma2(xaB, A0, h1b[2*q]));
            h1b[2*q+1] = ffma2(xbB, B1, ffma2(xaB, A1, h1b[2*q+1]));
        }
    }
    #pragma unroll
    for (int q = 0; q < 16; q++) { h1a[q] = gelu2(h1a[q]); h1b[q] = gelu2(h1b[q]); }

    // layer 4 (h2 arrays reused as geom accumulators)
    float accsA = s_b4[0], accsB = s_b4[0];
    #pragma unroll
    for (int q = 0; q < 16; q++) {
        float2 bb = f2(s_b4[1 + 2 * q], s_b4[2 + 2 * q]);
        h2a[q] = bb; h2b[q] = bb;
    }
    #pragma unroll
    for (int i = 0; i < 16; i++) {
        const float x0A = h1a[i].x, x1A = h1a[i].y;
        const float x0B = h1b[i].x, x1B = h1b[i].y;
        const float2 xaA = f2(x0A, x0A), xbA = f2(x1A, x1A);
        const float2 xaB = f2(x0B, x0B), xbB = f2(x1B, x1B);
        const float4* wr0 = s_w4g + (2 * i) * 8;
        const float4* wr1 = wr0 + 8;
        const float ws0 = s_w4s[2 * i], ws1 = s_w4s[2 * i + 1];
        accsA = fmaf(x1A, ws1, fmaf(x0A, ws0, accsA));
        accsB = fmaf(x1B, ws1, fmaf(x0B, ws0, accsB));
        #pragma unroll
        for (int q = 0; q < 8; q++) {
            float4 A = wr0[q], B = wr1[q];
            float2 A0 = f2(A.x, A.y), A1 = f2(A.z, A.w);
            float2 B0 = f2(B.x, B.y), B1 = f2(B.z, B.w);
            h2a[2*q]   = ffma2(xbA, B0, ffma2(xaA, A0, h2a[2*q]));
            h2a[2*q+1] = ffma2(xbA, B1, ffma2(xaA, A1, h2a[2*q+1]));
            h2b[2*q]   = ffma2(xbB, B0, ffma2(xaB, A0, h2b[2*q]));
            h2b[2*q+1] = ffma2(xbB, B1, ffma2(xaB, A1, h2b[2*q+1]));
        }
    }

    // ---- outputs: sdf scalar + direct STG.128 geom rows ----
    if (a0) {
        out[n0] = accsA;
        float4* gout = (float4*)(out + (size_t)N + (size_t)n0 * 32);
        #pragma unroll
        for (int q = 0; q < 8; q++) {
            float4 o;
            o.x = h2a[2*q].x;   o.y = h2a[2*q].y;
            o.z = h2a[2*q+1].x; o.w = h2a[2*q+1].y;
            gout[q] = o;
        }
    }
    if (a1) {
        out[n1] = accsB;
        float4* gout = (float4*)(out + (size_t)N + (size_t)n1 * 32);
        #pragma unroll
        for (int q = 0; q < 8; q++) {
            float4 o;
            o.x = h2b[2*q].x;   o.y = h2b[2*q].y;
            o.z = h2b[2*q+1].x; o.w = h2b[2*q+1].y;
            gout[q] = o;
        }
    }
}

extern "C" void kernel_launch(void* const* d_in, const int* in_sizes, int n_in,
                              void* d_out, int out_size)
{
    const float* points = (const float*)d_in[0];
    const int*   iter   = (const int*)  d_in[1];
    const float* tables = (const float*)d_in[2];
    const float* shifts = (const float*)d_in[3];
    const float* w1 = (const float*)d_in[4];  const float* b1 = (const float*)d_in[5];
    const float* w2 = (const float*)d_in[6];  const float* b2 = (const float*)d_in[7];
    const float* w3 = (const float*)d_in[8];  const float* b3 = (const float*)d_in[9];
    const float* w4 = (const float*)d_in[10]; const float* b4 = (const float*)d_in[11];

    const int N = in_sizes[0] / 3;

    const int grid1 = (N + 255) / 256;
    enc_kernel<<<grid1, 256>>>(points, iter, tables, shifts, N);

    const int grid2 = (N + MBLK * 2 - 1) / (MBLK * 2);
    mlp_kernel<<<grid2, MBLK>>>(points, iter,
                                w1, b1, w2, b2, w3, b3, w4, b4,
                                (float*)d_out, N);
}

// round 10
// speedup vs baseline: 1.0170x; 1.0170x over previous
#include <cuda_runtime.h>
#include <cstdint>
#include <math.h>

#define NLEV 24
#define CAPACITY (1u << 18)
#define MAXN 262144

// Post-GELU layer-1 activations, transposed: 16 float2 rows of length MAXN.
__device__ float2 g_h1[16 * MAXN];

union F2U { float2 f; unsigned long long u; };

// Packed dual-lane FMA / MUL (Blackwell f32x2 pipes).
__device__ __forceinline__ float2 ffma2(float2 a, float2 b, float2 c) {
    F2U A, B, C, D;
    A.f = a; B.f = b; C.f = c;
    asm("fma.rn.f32x2 %0, %1, %2, %3;" : "=l"(D.u) : "l"(A.u), "l"(B.u), "l"(C.u));
    return D.f;
}
__device__ __forceinline__ float2 mul2(float2 a, float2 b) {
    F2U A, B, D;
    A.f = a; B.f = b;
    asm("mul.rn.f32x2 %0, %1, %2;" : "=l"(D.u) : "l"(A.u), "l"(B.u));
    return D.f;
}
__device__ __forceinline__ float2 f2(float a, float b) { return make_float2(a, b); }

__device__ __forceinline__ float frcp(float x) {
    float r; asm("rcp.approx.f32 %0, %1;" : "=f"(r) : "f"(x)); return r;
}

// Packed-pair GELU, erf via A&S 7.1.25 (3-term, |err| <= 2.5e-5 abs).
// Validated R7/R9: end-to-end rel_err 1.55e-7 (threshold 1e-3).
__device__ __forceinline__ float2 gelu2(float2 v) {
    const float2 zc = f2(0.70710678118654752f, 0.70710678118654752f);
    float2 z  = mul2(v, zc);
    float2 az = f2(fabsf(z.x), fabsf(z.y));
    float2 den = ffma2(f2(0.47047f, 0.47047f), az, f2(1.0f, 1.0f));
    float2 t = f2(frcp(den.x), frcp(den.y));
    float2 p = ffma2(f2(0.7478556f, 0.7478556f), t, f2(-0.0958798f, -0.0958798f));
    p = ffma2(p, t, f2(0.3480242f, 0.3480242f));
    p = mul2(p, t);
    float2 zz = mul2(az, az);
    float2 e = f2(__expf(-zz.x), __expf(-zz.y));
    float2 pe = mul2(p, e);
    float2 er = f2(copysignf(1.0f - pe.x, z.x), copysignf(1.0f - pe.y, z.y));
    float2 hv = mul2(v, f2(0.5f, 0.5f));
    return ffma2(hv, er, hv);
}

// ============ K1: permutohedral encoding + layer-1 fold + GELU ============

#define EBLK 128

__global__ __launch_bounds__(EBLK, 5)
void encfold_kernel(const float* __restrict__ points,
                    const int*   __restrict__ iter_nr,
                    const float* __restrict__ tables,
                    const float* __restrict__ shifts,
                    const float* __restrict__ w1, const float* __restrict__ b1,
                    int N)
{
    __shared__ float4 s_w1[51 * 8];
    __shared__ float2 s_b1[16];
    __shared__ float  s_shift[NLEV * 3];
    __shared__ float  s_invsc[NLEV];
    __shared__ float  s_win[NLEV];
    __shared__ int    s_nlev;

    const int tid = threadIdx.x;
    {
        const float4* g1 = (const float4*)w1;
        for (int i = tid; i < 51 * 8; i += EBLK) s_w1[i] = g1[i];
    }
    if (tid < 16) s_b1[tid] = ((const float2*)b1)[tid];
    if (tid < NLEV * 3) s_shift[tid] = shifts[tid];
    if (tid < NLEV) {
        // SCALES = geomspace(1, 1e-4, 24) = 10^(i * (-4/23)) in float64 -> f32
        double step = -4.0 / 23.0;
        float sc = (float)pow(10.0, step * (double)tid);
        s_invsc[tid] = 1.0f / sc;
        float t = fminf(fmaxf((float)iter_nr[0] / 10000.0f, 0.0f), 1.0f);
        float alpha = (0.3f + 0.7f * t) * (float)NLEV;
        float x = fminf(fmaxf(alpha - (float)tid, 0.0f), 1.0f);
        s_win[tid] = 0.5f * (1.0f - cosf(3.14159265358979323846f * x));
        if (tid == 0) {
            int na = (int)ceilf(alpha);
            if (na > NLEV) na = NLEV;
            if (na < 0) na = 0;
            s_nlev = na;
        }
    }
    __syncthreads();

    const int n = blockIdx.x * EBLK + tid;
    if (n >= N) return;
    const int nlev = s_nlev;

    const float p0 = __ldg(points + n * 3 + 0);
    const float p1 = __ldg(points + n * 3 + 1);
    const float p2 = __ldg(points + n * 3 + 2);
    const float2* tab2 = (const float2*)tables;

    // ---- layer-1 accumulator, seeded with bias + point*0.001 rows (48..50)
    float2 h1[16];
    {
        const float2 xa = f2(p0 * 0.001f, p0 * 0.001f);
        const float2 xb = f2(p1 * 0.001f, p1 * 0.001f);
        const float2 xc = f2(p2 * 0.001f, p2 * 0.001f);
        const float4* wa = s_w1 + 48 * 8;
        const float4* wb = s_w1 + 49 * 8;
        const float4* wc = s_w1 + 50 * 8;
        #pragma unroll
        for (int q = 0; q < 8; q++) {
            float4 A = wa[q], B = wb[q], C = wc[q];
            float2 v0 = ffma2(xa, f2(A.x, A.y), s_b1[2*q]);
            v0 = ffma2(xb, f2(B.x, B.y), v0);
            h1[2*q] = ffma2(xc, f2(C.x, C.y), v0);
            float2 v1 = ffma2(xa, f2(A.z, A.w), s_b1[2*q+1]);
            v1 = ffma2(xb, f2(B.z, B.w), v1);
            h1[2*q+1] = ffma2(xc, f2(C.z, C.w), v1);
        }
    }

    const float SF0 = 2.30940107675850341796875f;  // 4*sqrt(2/3)/sqrt(1*2)
    const float SF1 = 1.33333333333333333f;
    const float SF2 = 0.94280904158206336f;
    const float RM  = 12582912.0f;                 // 1.5 * 2^23
    const int   RI  = 0x4B400000;                  // bit pattern of RM

    #pragma unroll 1
    for (int lev = 0; lev < nlev; ++lev) {
        const float inv = s_invsc[lev];
        const float cf0 = fmaf(p0, inv, s_shift[lev * 3 + 0]) * SF0;
        const float cf1 = fmaf(p1, inv, s_shift[lev * 3 + 1]) * SF1;
        const float cf2 = fmaf(p2, inv, s_shift[lev * 3 + 2]) * SF2;

        const float S2 = cf2;
        const float S1 = cf2 + cf1;
        const float S0 = S1 + cf0;

        float e[4];
        e[0] = S0;
        e[1] = S1 - cf0;
        e[2] = S2 - 2.0f * cf1;
        e[3] = -3.0f * cf2;

        float u[4];
        int   m[4];
        #pragma unroll
        for (int i = 0; i < 4; i++) {
            const float q = fmaf(e[i], 0.25f, RM);     // round-half-even
            m[i] = __float_as_int(q) - RI;             // rint(e/4) as int
            const float t = q - RM;                    // rint(e/4) float (exact)
            u[i] = fmaf(e[i], 0.25f, -t);              // delta (exact)
        }

        const int sumv = m[0] + m[1] + m[2] + m[3];

        // rank via 6 antisymmetric compares (stable argsort(argsort(-u)))
        const int t01 = (u[1] > u[0]);
        const int t02 = (u[2] > u[0]);
        const int t03 = (u[3] > u[0]);
        const int t12 = (u[2] > u[1]);
        const int t13 = (u[3] > u[1]);
        const int t23 = (u[3] > u[2]);

        int rk[4];
        rk[0] = sumv +     t01 + t02 + t03;
        rk[1] = sumv + 1 - t01 + t12 + t13;
        rk[2] = sumv + 2 - t02 - t12 + t23;
        rk[3] = sumv + 3 - t03 - t13 - t23;

        #pragma unroll
        for (int i = 0; i < 4; i++) {
            if (rk[i] < 0)      { rk[i] += 4; m[i] += 1; u[i] -= 1.0f; }
            else if (rk[i] > 3) { rk[i] -= 4; m[i] -= 1; u[i] += 1.0f; }
        }

        // barycentric weights
        float bq0 = 0.f, bq1 = 0.f, bq2 = 0.f, bq3 = 0.f, bq4 = 0.f;
        #pragma unroll
        for (int i = 0; i < 4; i++) {
            const int id = 3 - rk[i];
            const float dv = u[i];
            if (id == 0)      { bq0 += dv; bq1 -= dv; }
            else if (id == 1) { bq1 += dv; bq2 -= dv; }
            else if (id == 2) { bq2 += dv; bq3 -= dv; }
            else              { bq3 += dv; bq4 -= dv; }
        }
        const float wl = s_win[lev];
        float w0 = (bq0 + 1.0f + bq4) * wl;
        float w1v = bq1 * wl;
        float w2v = bq2 * wl;
        float w3v = bq3 * wl;

        // vertex keys: key_i(k) = 4*m_i + ((k + rk_i) & 3) - rk_i
        const int b0 = 4 * m[0] - rk[0];
        const int b1v = 4 * m[1] - rk[1];
        const int b2v = 4 * m[2] - rk[2];
        const float2* tab = tab2 + (size_t)lev * CAPACITY;

        uint32_t idx[4];
        #pragma unroll
        for (int k = 0; k < 4; k++) {
            const uint32_t k0 = (uint32_t)(b0  + ((k + rk[0]) & 3));
            const uint32_t k1 = (uint32_t)(b1v + ((k + rk[1]) & 3));
            const uint32_t k2 = (uint32_t)(b2v + ((k + rk[2]) & 3));
            const uint32_t h = k0 ^ (k1 * 2654435761u) ^ (k2 * 805459861u);
            idx[k] = h & (CAPACITY - 1u);
        }
        const float2 g0 = __ldg(tab + idx[0]);
        const float2 g1 = __ldg(tab + idx[1]);
        const float2 g2 = __ldg(tab + idx[2]);
        const float2 g3 = __ldg(tab + idx[3]);

        float fx = g0.x * w0, fy = g0.y * w0;
        fx = fmaf(g1.x, w1v, fx); fy = fmaf(g1.y, w1v, fy);
        fx = fmaf(g2.x, w2v, fx); fy = fmaf(g2.y, w2v, fy);
        fx = fmaf(g3.x, w3v, fx); fy = fmaf(g3.y, w3v, fy);

        // fold into layer-1 hidden: rows 2*lev, 2*lev+1 of w1
        const float2 f0 = f2(fx, fx);
        const float2 f1 = f2(fy, fy);
        const float4* ra = s_w1 + (2 * lev) * 8;
        #pragma unroll
        for (int q = 0; q < 8; q++) {
            float4 A = ra[q];       // row 2*lev
            float4 B = ra[q + 8];   // row 2*lev+1
            float2 v0 = ffma2(f0, f2(A.x, A.y), h1[2*q]);
            h1[2*q] = ffma2(f1, f2(B.x, B.y), v0);
            float2 v1 = ffma2(f0, f2(A.z, A.w), h1[2*q+1]);
            h1[2*q+1] = ffma2(f1, f2(B.z, B.w), v1);
        }
    }

    // GELU + transposed coalesced store (16 STG.64)
    #pragma unroll
    for (int q = 0; q < 16; q++)
        g_h1[(size_t)q * MAXN + n] = gelu2(h1[q]);
}

// ================= K2: layers 2..4 of the MLP =================

#define MBLK 128

__global__ __launch_bounds__(MBLK, 5)
void mlp_kernel(const float* __restrict__ w2, const float* __restrict__ b2,
                const float* __restrict__ w3, const float* __restrict__ b3,
                const float* __restrict__ w4, const float* __restrict__ b4,
                float* __restrict__ out, int N)
{
    __shared__ float4 s_w2[32 * 8];
    __shared__ float4 s_w3[32 * 8];
    __shared__ float4 s_w4g[32 * 8];    // geom cols 1..32
    __shared__ float  s_w4s[32];        // sdf column 0
    __shared__ float2 s_b2[16];
    __shared__ float2 s_b3[16];
    __shared__ float  s_b4[33];

    const int tid = threadIdx.x;
    {
        const float4* g2 = (const float4*)w2;
        const float4* g3 = (const float4*)w3;
        for (int i = tid; i < 32 * 8; i += MBLK) s_w2[i] = g2[i];
        for (int i = tid; i < 32 * 8; i += MBLK) s_w3[i] = g3[i];
    }
    {
        float* w4g = (float*)s_w4g;
        for (int i = tid; i < 32 * 33; i += MBLK) {
            int r = i / 33, c = i - r * 33;
            float v = w4[i];
            if (c == 0) s_w4s[r] = v; else w4g[r * 32 + (c - 1)] = v;
        }
    }
    if (tid < 16) {
        s_b2[tid] = ((const float2*)b2)[tid];
        s_b3[tid] = ((const float2*)b3)[tid];
    }
    if (tid < 33) s_b4[tid] = b4[tid];
    __syncthreads();

    const int n = blockIdx.x * MBLK + tid;
    if (n >= N) return;

    // ---- load post-GELU h1 (coalesced LDG.64 x16) ----
    float2 h1[16];
    #pragma unroll
    for (int q = 0; q < 16; q++)
        h1[q] = g_h1[(size_t)q * MAXN + n];

    // ---- layer 2 ----
    float2 h2[16];
    #pragma unroll
    for (int q = 0; q < 16; q++) h2[q] = s_b2[q];
    #pragma unroll
    for (int i = 0; i < 16; i++) {
        const float2 xa = f2(h1[i].x, h1[i].x);
        const float2 xb = f2(h1[i].y, h1[i].y);
        const float4* wr0 = s_w2 + (2 * i) * 8;
        const float4* wr1 = wr0 + 8;
        #pragma unroll
        for (int q = 0; q < 8; q++) {
            float4 A = wr0[q], B = wr1[q];
            float2 v0 = ffma2(xa, f2(A.x, A.y), h2[2*q]);
            h2[2*q] = ffma2(xb, f2(B.x, B.y), v0);
            float2 v1 = ffma2(xa, f2(A.z, A.w), h2[2*q+1]);
            h2[2*q+1] = ffma2(xb, f2(B.z, B.w), v1);
        }
    }
    #pragma unroll
    for (int q = 0; q < 16; q++) h2[q] = gelu2(h2[q]);

    // ---- layer 3 (into h1) ----
    #pragma unroll
    for (int q = 0; q < 16; q++) h1[q] = s_b3[q];
    #pragma unroll
    for (int i = 0; i < 16; i++) {
        const float2 xa = f2(h2[i].x, h2[i].x);
        const float2 xb = f2(h2[i].y, h2[i].y);
        const float4* wr0 = s_w3 + (2 * i) * 8;
        const float4* wr1 = wr0 + 8;
        #pragma unroll
        for (int q = 0; q < 8; q++) {
            float4 A = wr0[q], B = wr1[q];
            float2 v0 = ffma2(xa, f2(A.x, A.y), h1[2*q]);
            h1[2*q] = ffma2(xb, f2(B.x, B.y), v0);
            float2 v1 = ffma2(xa, f2(A.z, A.w), h1[2*q+1]);
            h1[2*q+1] = ffma2(xb, f2(B.z, B.w), v1);
        }
    }
    #pragma unroll
    for (int q = 0; q < 16; q++) h1[q] = gelu2(h1[q]);

    // ---- layer 4 (h2 reused as geom accumulator) ----
    float acc0 = s_b4[0];
    #pragma unroll
    for (int q = 0; q < 16; q++)
        h2[q] = f2(s_b4[1 + 2 * q], s_b4[2 + 2 * q]);
    #pragma unroll
    for (int i = 0; i < 16; i++) {
        const float x0 = h1[i].x, x1 = h1[i].y;
        const float2 xa = f2(x0, x0);
        const float2 xb = f2(x1, x1);
        const float4* wr0 = s_w4g + (2 * i) * 8;
        const float4* wr1 = wr0 + 8;
        acc0 = fmaf(x1, s_w4s[2 * i + 1], fmaf(x0, s_w4s[2 * i], acc0));
        #pragma unroll
        for (int q = 0; q < 8; q++) {
            float4 A = wr0[q], B = wr1[q];
            float2 v0 = ffma2(xa, f2(A.x, A.y), h2[2*q]);
            h2[2*q] = ffma2(xb, f2(B.x, B.y), v0);
            float2 v1 = ffma2(xa, f2(A.z, A.w), h2[2*q+1]);
            h2[2*q+1] = ffma2(xb, f2(B.z, B.w), v1);
        }
    }

    out[n] = acc0;
    float4* gout = (float4*)(out + (size_t)N + (size_t)n * 32);
    #pragma unroll
    for (int q = 0; q < 8; q++) {
        float4 o;
        o.x = h2[2*q].x;   o.y = h2[2*q].y;
        o.z = h2[2*q+1].x; o.w = h2[2*q+1].y;
        gout[q] = o;
    }
}

extern "C" void kernel_launch(void* const* d_in, const int* in_sizes, int n_in,
                              void* d_out, int out_size)
{
    const float* points = (const float*)d_in[0];
    const int*   iter   = (const int*)  d_in[1];
    const float* tables = (const float*)d_in[2];
    const float* shifts = (const float*)d_in[3];
    const float* w1 = (const float*)d_in[4];  const float* b1 = (const float*)d_in[5];
    const float* w2 = (const float*)d_in[6];  const float* b2 = (const float*)d_in[7];
    const float* w3 = (const float*)d_in[8];  const float* b3 = (const float*)d_in[9];
    const float* w4 = (const float*)d_in[10]; const float* b4 = (const float*)d_in[11];

    const int N = in_sizes[0] / 3;

    const int grid1 = (N + EBLK - 1) / EBLK;
    encfold_kernel<<<grid1, EBLK>>>(points, iter, tables, shifts, w1, b1, N);

    const int grid2 = (N + MBLK - 1) / MBLK;
    mlp_kernel<<<grid2, MBLK>>>(w2, b2, w3, b3, w4, b4, (float*)d_out, N);
}

// round 11
// speedup vs baseline: 1.0799x; 1.0619x over previous
#include <cuda_runtime.h>
#include <cstdint>
#include <math.h>

#define NLEV 24
#define CAPACITY (1u << 18)
#define MAXN 262144

// Per-level features, transposed: row lev holds float2 (fx,fy) for all points.
__device__ float2 g_enc[NLEV * MAXN];

union F2U { float2 f; unsigned long long u; };

// Packed dual-lane FMA / MUL (Blackwell f32x2 pipes).
__device__ __forceinline__ float2 ffma2(float2 a, float2 b, float2 c) {
    F2U A, B, C, D;
    A.f = a; B.f = b; C.f = c;
    asm("fma.rn.f32x2 %0, %1, %2, %3;" : "=l"(D.u) : "l"(A.u), "l"(B.u), "l"(C.u));
    return D.f;
}
__device__ __forceinline__ float2 mul2(float2 a, float2 b) {
    F2U A, B, D;
    A.f = a; B.f = b;
    asm("mul.rn.f32x2 %0, %1, %2;" : "=l"(D.u) : "l"(A.u), "l"(B.u));
    return D.f;
}
__device__ __forceinline__ float2 f2(float a, float b) { return make_float2(a, b); }

__device__ __forceinline__ float frcp(float x) {
    float r; asm("rcp.approx.f32 %0, %1;" : "=f"(r) : "f"(x)); return r;
}

// Packed-pair GELU, erf via A&S 7.1.25 (3-term, |err| <= 2.5e-5 abs).
// Validated R7/R9/R10: end-to-end rel_err 1.55e-7 (threshold 1e-3).
__device__ __forceinline__ float2 gelu2(float2 v) {
    const float2 zc = f2(0.70710678118654752f, 0.70710678118654752f);
    float2 z  = mul2(v, zc);
    float2 az = f2(fabsf(z.x), fabsf(z.y));
    float2 den = ffma2(f2(0.47047f, 0.47047f), az, f2(1.0f, 1.0f));
    float2 t = f2(frcp(den.x), frcp(den.y));
    float2 p = ffma2(f2(0.7478556f, 0.7478556f), t, f2(-0.0958798f, -0.0958798f));
    p = ffma2(p, t, f2(0.3480242f, 0.3480242f));
    p = mul2(p, t);
    float2 zz = mul2(az, az);
    float2 e = f2(__expf(-zz.x), __expf(-zz.y));
    float2 pe = mul2(p, e);
    float2 er = f2(copysignf(1.0f - pe.x, z.x), copysignf(1.0f - pe.y, z.y));
    float2 hv = mul2(v, f2(0.5f, 0.5f));
    return ffma2(hv, er, hv);
}

// ======================= K1: permutohedral encoding =======================

__global__ __launch_bounds__(256, 4)
void enc_kernel(const float* __restrict__ points,
                const int*   __restrict__ iter_nr,
                const float* __restrict__ tables,
                const float* __restrict__ shifts,
                int N)
{
    __shared__ float s_shift[NLEV * 3];
    __shared__ float s_invsc[NLEV];
    __shared__ float s_win[NLEV];
    __shared__ int   s_nlev;

    const int tid = threadIdx.x;
    if (tid < NLEV * 3) s_shift[tid] = shifts[tid];
    if (tid < NLEV) {
        // SCALES = geomspace(1, 1e-4, 24) = 10^(i * (-4/23)) in float64 -> f32
        double step = -4.0 / 23.0;
        float sc = (float)pow(10.0, step * (double)tid);
        s_invsc[tid] = 1.0f / sc;
        float t = fminf(fmaxf((float)iter_nr[0] / 10000.0f, 0.0f), 1.0f);
        float alpha = (0.3f + 0.7f * t) * (float)NLEV;
        float x = fminf(fmaxf(alpha - (float)tid, 0.0f), 1.0f);
        s_win[tid] = 0.5f * (1.0f - cosf(3.14159265358979323846f * x));
        if (tid == 0) {
            int na = (int)ceilf(alpha);
            if (na > NLEV) na = NLEV;
            if (na < 0) na = 0;
            s_nlev = na;
        }
    }
    __syncthreads();

    const int n = blockIdx.x * 256 + tid;
    if (n >= N) return;
    const int nlev = s_nlev;

    const float p0 = __ldg(points + n * 3 + 0);
    const float p1 = __ldg(points + n * 3 + 1);
    const float p2 = __ldg(points + n * 3 + 2);
    const float2* tab2 = (const float2*)tables;

    const float SF0 = 2.30940107675850341796875f;  // 4*sqrt(2/3)/sqrt(1*2)
    const float SF1 = 1.33333333333333333f;
    const float SF2 = 0.94280904158206336f;
    const float RM  = 12582912.0f;                 // 1.5 * 2^23
    const int   RI  = 0x4B400000;                  // bit pattern of RM

    #pragma unroll 1
    for (int lev = 0; lev < nlev; ++lev) {
        const float inv = s_invsc[lev];
        const float cf0 = fmaf(p0, inv, s_shift[lev * 3 + 0]) * SF0;
        const float cf1 = fmaf(p1, inv, s_shift[lev * 3 + 1]) * SF1;
        const float cf2 = fmaf(p2, inv, s_shift[lev * 3 + 2]) * SF2;

        const float S2 = cf2;
        const float S1 = cf2 + cf1;
        const float S0 = S1 + cf0;

        float e[4];
        e[0] = S0;
        e[1] = S1 - cf0;
        e[2] = S2 - 2.0f * cf1;
        e[3] = -3.0f * cf2;

        float u[4];
        int   m[4];
        #pragma unroll
        for (int i = 0; i < 4; i++) {
            const float q = fmaf(e[i], 0.25f, RM);     // round-half-even
            m[i] = __float_as_int(q) - RI;             // rint(e/4) as int
            const float t = q - RM;                    // rint(e/4) float (exact)
            u[i] = fmaf(e[i], 0.25f, -t);              // delta (exact)
        }

        const int sumv = m[0] + m[1] + m[2] + m[3];

        // rank via 6 antisymmetric compares (stable argsort(argsort(-u)))
        const int t01 = (u[1] > u[0]);
        const int t02 = (u[2] > u[0]);
        const int t03 = (u[3] > u[0]);
        const int t12 = (u[2] > u[1]);
        const int t13 = (u[3] > u[1]);
        const int t23 = (u[3] > u[2]);

        int rk[4];
        rk[0] = sumv +     t01 + t02 + t03;
        rk[1] = sumv + 1 - t01 + t12 + t13;
        rk[2] = sumv + 2 - t02 - t12 + t23;
        rk[3] = sumv + 3 - t03 - t13 - t23;

        #pragma unroll
        for (int i = 0; i < 4; i++) {
            if (rk[i] < 0)      { rk[i] += 4; m[i] += 1; u[i] -= 1.0f; }
            else if (rk[i] > 3) { rk[i] -= 4; m[i] -= 1; u[i] += 1.0f; }
        }

        // barycentric weights
        float bq0 = 0.f, bq1 = 0.f, bq2 = 0.f, bq3 = 0.f, bq4 = 0.f;
        #pragma unroll
        for (int i = 0; i < 4; i++) {
            const int id = 3 - rk[i];
            const float dv = u[i];
            if (id == 0)      { bq0 += dv; bq1 -= dv; }
            else if (id == 1) { bq1 += dv; bq2 -= dv; }
            else if (id == 2) { bq2 += dv; bq3 -= dv; }
            else              { bq3 += dv; bq4 -= dv; }
        }
        const float wl = s_win[lev];
        float w0 = (bq0 + 1.0f + bq4) * wl;
        float w1 = bq1 * wl;
        float w2 = bq2 * wl;
        float w3 = bq3 * wl;

        // vertex keys: key_i(k) = 4*m_i + ((k + rk_i) & 3) - rk_i
        const int b0 = 4 * m[0] - rk[0];
        const int b1 = 4 * m[1] - rk[1];
        const int b2 = 4 * m[2] - rk[2];
        const float2* tab = tab2 + (size_t)lev * CAPACITY;

        uint32_t idx[4];
        #pragma unroll
        for (int k = 0; k < 4; k++) {
            const uint32_t k0 = (uint32_t)(b0 + ((k + rk[0]) & 3));
            const uint32_t k1 = (uint32_t)(b1 + ((k + rk[1]) & 3));
            const uint32_t k2 = (uint32_t)(b2 + ((k + rk[2]) & 3));
            const uint32_t h = k0 ^ (k1 * 2654435761u) ^ (k2 * 805459861u);
            idx[k] = h & (CAPACITY - 1u);
        }
        const float2 g0 = __ldg(tab + idx[0]);
        const float2 g1 = __ldg(tab + idx[1]);
        const float2 g2 = __ldg(tab + idx[2]);
        const float2 g3 = __ldg(tab + idx[3]);

        float fx = g0.x * w0, fy = g0.y * w0;
        fx = fmaf(g1.x, w1, fx); fy = fmaf(g1.y, w1, fy);
        fx = fmaf(g2.x, w2, fx); fy = fmaf(g2.y, w2, fy);
        fx = fmaf(g3.x, w3, fx); fy = fmaf(g3.y, w3, fy);

        // one coalesced STG.64 per level
        g_enc[(size_t)lev * MAXN + n] = f2(fx, fy);
    }
}

// ============ K2: layer-1 fold + full MLP (1 pt/thread, gelu2) ============

#define MBLK 128

__global__ __launch_bounds__(MBLK, 5)
void mlp_kernel(const float* __restrict__ points,
                const int*   __restrict__ iter_nr,
                const float* __restrict__ w1, const float* __restrict__ b1,
                const float* __restrict__ w2, const float* __restrict__ b2,
                const float* __restrict__ w3, const float* __restrict__ b3,
                const float* __restrict__ w4, const float* __restrict__ b4,
                float* __restrict__ out, int N)
{
    __shared__ float4 s_w1[51 * 8];
    __shared__ float4 s_w2[32 * 8];
    __shared__ float4 s_w3[32 * 8];
    __shared__ float4 s_w4g[32 * 8];    // geom cols 1..32
    __shared__ float  s_w4s[32];        // sdf column 0
    __shared__ float2 s_b1[16];
    __shared__ float2 s_b2[16];
    __shared__ float2 s_b3[16];
    __shared__ float  s_b4[33];
    __shared__ int    s_nlev;

    const int tid = threadIdx.x;

    {
        const float4* g1 = (const float4*)w1;
        const float4* g2 = (const float4*)w2;
        const float4* g3 = (const float4*)w3;
        for (int i = tid; i < 51 * 8; i += MBLK) s_w1[i] = g1[i];
        for (int i = tid; i < 32 * 8; i += MBLK) s_w2[i] = g2[i];
        for (int i = tid; i < 32 * 8; i += MBLK) s_w3[i] = g3[i];
    }
    {
        float* w4g = (float*)s_w4g;
        for (int i = tid; i < 32 * 33; i += MBLK) {
            int r = i / 33, c = i - r * 33;
            float v = w4[i];
            if (c == 0) s_w4s[r] = v; else w4g[r * 32 + (c - 1)] = v;
        }
    }
    if (tid < 16) {
        s_b1[tid] = ((const float2*)b1)[tid];
        s_b2[tid] = ((const float2*)b2)[tid];
        s_b3[tid] = ((const float2*)b3)[tid];
    }
    if (tid < 33) s_b4[tid] = b4[tid];
    if (tid == 0) {
        float t = fminf(fmaxf((float)iter_nr[0] / 10000.0f, 0.0f), 1.0f);
        float alpha = (0.3f + 0.7f * t) * (float)NLEV;
        int na = (int)ceilf(alpha);
        if (na > NLEV) na = NLEV;
        if (na < 0) na = 0;
        s_nlev = na;
    }
    __syncthreads();

    const int n = blockIdx.x * MBLK + tid;
    if (n >= N) return;
    const int nlev = s_nlev;

    const float p0 = __ldg(points + n * 3 + 0);
    const float p1 = __ldg(points + n * 3 + 1);
    const float p2 = __ldg(points + n * 3 + 2);

    // ---- layer-1 accumulator, seeded with bias + point*0.001 rows (48..50)
    float2 h1[16];
    {
        const float2 xa = f2(p0 * 0.001f, p0 * 0.001f);
        const float2 xb = f2(p1 * 0.001f, p1 * 0.001f);
        const float2 xc = f2(p2 * 0.001f, p2 * 0.001f);
        const float4* wa = s_w1 + 48 * 8;
        const float4* wb = s_w1 + 49 * 8;
        const float4* wc = s_w1 + 50 * 8;
        #pragma unroll
        for (int q = 0; q < 8; q++) {
            float4 A = wa[q], B = wb[q], C = wc[q];
            float2 v0 = ffma2(xa, f2(A.x, A.y), s_b1[2*q]);
            v0 = ffma2(xb, f2(B.x, B.y), v0);
            h1[2*q] = ffma2(xc, f2(C.x, C.y), v0);
            float2 v1 = ffma2(xa, f2(A.z, A.w), s_b1[2*q+1]);
            v1 = ffma2(xb, f2(B.z, B.w), v1);
            h1[2*q+1] = ffma2(xc, f2(C.z, C.w), v1);
        }
    }

    // ---- fold encoded features (coalesced LDG.64, L2-hot) into layer 1 ----
    #pragma unroll 1
    for (int lev = 0; lev < nlev; ++lev) {
        const float2 fe = g_enc[(size_t)lev * MAXN + n];
        const float2 f0 = f2(fe.x, fe.x);
        const float2 f1 = f2(fe.y, fe.y);
        const float4* ra = s_w1 + (2 * lev) * 8;
        #pragma unroll
        for (int q = 0; q < 8; q++) {
            float4 A = ra[q];       // row 2*lev
            float4 B = ra[q + 8];   // row 2*lev+1
            float2 v0 = ffma2(f0, f2(A.x, A.y), h1[2*q]);
            h1[2*q] = ffma2(f1, f2(B.x, B.y), v0);
            float2 v1 = ffma2(f0, f2(A.z, A.w), h1[2*q+1]);
            h1[2*q+1] = ffma2(f1, f2(B.z, B.w), v1);
        }
    }

    // ---- layers 2..4 ----
    #pragma unroll
    for (int q = 0; q < 16; q++) h1[q] = gelu2(h1[q]);

    float2 h2[16];
    #pragma unroll
    for (int q = 0; q < 16; q++) h2[q] = s_b2[q];
    #pragma unroll
    for (int i = 0; i < 16; i++) {
        const float2 xa = f2(h1[i].x, h1[i].x);
        const float2 xb = f2(h1[i].y, h1[i].y);
        const float4* wr0 = s_w2 + (2 * i) * 8;
        const float4* wr1 = wr0 + 8;
        #pragma unroll
        for (int q = 0; q < 8; q++) {
            float4 A = wr0[q], B = wr1[q];
            float2 v0 = ffma2(xa, f2(A.x, A.y), h2[2*q]);
            h2[2*q] = ffma2(xb, f2(B.x, B.y), v0);
            float2 v1 = ffma2(xa, f2(A.z, A.w), h2[2*q+1]);
            h2[2*q+1] = ffma2(xb, f2(B.z, B.w), v1);
        }
    }
    #pragma unroll
    for (int q = 0; q < 16; q++) h2[q] = gelu2(h2[q]);

    #pragma unroll
    for (int q = 0; q < 16; q++) h1[q] = s_b3[q];
    #pragma unroll
    for (int i = 0; i < 16; i++) {
        const float2 xa = f2(h2[i].x, h2[i].x);
        const float2 xb = f2(h2[i].y, h2[i].y);
        const float4* wr0 = s_w3 + (2 * i) * 8;
        const float4* wr1 = wr0 + 8;
        #pragma unroll
        for (int q = 0; q < 8; q++) {
            float4 A = wr0[q], B = wr1[q];
            float2 v0 = ffma2(xa, f2(A.x, A.y), h1[2*q]);
            h1[2*q] = ffma2(xb, f2(B.x, B.y), v0);
            float2 v1 = ffma2(xa, f2(A.z, A.w), h1[2*q+1]);
            h1[2*q+1] = ffma2(xb, f2(B.z, B.w), v1);
        }
    }
    #pragma unroll
    for (int q = 0; q < 16; q++) h1[q] = gelu2(h1[q]);

    // layer 4 (h2 reused as geom accumulator)
    float acc0 = s_b4[0];
    #pragma unroll
    for (int q = 0; q < 16; q++)
        h2[q] = f2(s_b4[1 + 2 * q], s_b4[2 + 2 * q]);
    #pragma unroll
    for (int i = 0; i < 16; i++) {
        const float x0 = h1[i].x, x1 = h1[i].y;
        const float2 xa = f2(x0, x0);
        const float2 xb = f2(x1, x1);
        const float4* wr0 = s_w4g + (2 * i) * 8;
        const float4* wr1 = wr0 + 8;
        acc0 = fmaf(x1, s_w4s[2 * i + 1], fmaf(x0, s_w4s[2 * i], acc0));
        #pragma unroll
        for (int q = 0; q < 8; q++) {
            float4 A = wr0[q], B = wr1[q];
            float2 v0 = ffma2(xa, f2(A.x, A.y), h2[2*q]);
            h2[2*q] = ffma2(xb, f2(B.x, B.y), v0);
            float2 v1 = ffma2(xa, f2(A.z, A.w), h2[2*q+1]);
            h2[2*q+1] = ffma2(xb, f2(B.z, B.w), v1);
        }
    }

    out[n] = acc0;
    float4* gout = (float4*)(out + (size_t)N + (size_t)n * 32);
    #pragma unroll
    for (int q = 0; q < 8; q++) {
        float4 o;
        o.x = h2[2*q].x;   o.y = h2[2*q].y;
        o.z = h2[2*q+1].x; o.w = h2[2*q+1].y;
        gout[q] = o;
    }
}

extern "C" void kernel_launch(void* const* d_in, const int* in_sizes, int n_in,
                              void* d_out, int out_size)
{
    const float* points = (const float*)d_in[0];
    const int*   iter   = (const int*)  d_in[1];
    const float* tables = (const float*)d_in[2];
    const float* shifts = (const float*)d_in[3];
    const float* w1 = (const float*)d_in[4];  const float* b1 = (const float*)d_in[5];
    const float* w2 = (const float*)d_in[6];  const float* b2 = (const float*)d_in[7];
    const float* w3 = (const float*)d_in[8];  const float* b3 = (const float*)d_in[9];
    const float* w4 = (const float*)d_in[10]; const float* b4 = (const float*)d_in[11];

    const int N = in_sizes[0] / 3;

    const int grid1 = (N + 255) / 256;
    enc_kernel<<<grid1, 256>>>(points, iter, tables, shifts, N);

    const int grid2 = (N + MBLK - 1) / MBLK;
    mlp_kernel<<<grid2, MBLK>>>(points, iter,
                                w1, b1, w2, b2, w3, b3, w4, b4,
                                (float*)d_out, N);
}